// round 4
// baseline (speedup 1.0000x reference)
#include <cuda_runtime.h>
#include <cuda_bf16.h>

// Problem constants
#define Bv   2
#define Nv   2048
#define Ev   1024
#define Hv   16
#define Dv   64
#define BMv  32
#define TRv  64          // Tr = Tc = 64
#define KSEL 12          // int(0.2 * 64)
#define Mrows (Bv * Nv)  // 4096

// ---------------- scratch (static device globals; no allocation) -------------
__device__ float g_Q[Bv * Hv * Nv * Dv];   // [b,h,n,d] 16 MB
__device__ float g_K[Bv * Hv * Nv * Dv];
__device__ float g_V[Bv * Hv * Nv * Dv];
__device__ float g_O[Bv * Nv * Ev];        // [b,n,h,d] 16 MB
__device__ float g_Qp[Bv * Hv * TRv * Dv]; // pooled Q  [bh,t,d]
__device__ float g_Kp[Bv * Hv * TRv * Dv]; // pooled K  [bh,c,d]
__device__ float g_S[TRv * TRv];           // block scores [t,c]
__device__ int   g_idx[TRv * KSEL];        // top-k block indices per t

// ---------------- 128x128x8 fp32 GEMM tile (shared by both GEMMs) ------------
// A: [M,1024] row-major (row base = blockIdx.y*128)
// W: [1024,1024] row-major (col base = blockIdx.x*128)
__device__ __forceinline__ void sgemm_tile128(const float* __restrict__ A,
                                              const float* __restrict__ W,
                                              float acc[8][8])
{
    __shared__ float As[8][128];
    __shared__ float Bs[8][128];
    const int tid  = threadIdx.x;
    const int arow = tid >> 1;          // 0..127
    const int acol = (tid & 1) * 4;     // 0 or 4
    const int brow = tid >> 5;          // 0..7
    const int bcol = (tid & 31) * 4;    // 0..124
    const int ty   = tid >> 4;          // 0..15
    const int tx   = tid & 15;          // 0..15

    const float* Aptr = A + (blockIdx.y * 128 + arow) * 1024 + acol;
    const float* Wptr = W + brow * 1024 + blockIdx.x * 128 + bcol;

    for (int kt = 0; kt < 1024; kt += 8) {
        // stage global loads before sync so they overlap previous compute
        float4 av = *reinterpret_cast<const float4*>(Aptr + kt);
        float4 wv = *reinterpret_cast<const float4*>(Wptr + kt * 1024);
        __syncthreads();
        As[acol + 0][arow] = av.x;
        As[acol + 1][arow] = av.y;
        As[acol + 2][arow] = av.z;
        As[acol + 3][arow] = av.w;
        *reinterpret_cast<float4*>(&Bs[brow][bcol]) = wv;
        __syncthreads();
#pragma unroll
        for (int k = 0; k < 8; k++) {
            float4 a0 = *reinterpret_cast<const float4*>(&As[k][ty * 8]);
            float4 a1 = *reinterpret_cast<const float4*>(&As[k][ty * 8 + 4]);
            float4 b0 = *reinterpret_cast<const float4*>(&Bs[k][tx * 8]);
            float4 b1 = *reinterpret_cast<const float4*>(&Bs[k][tx * 8 + 4]);
            float a[8] = {a0.x, a0.y, a0.z, a0.w, a1.x, a1.y, a1.z, a1.w};
            float b[8] = {b0.x, b0.y, b0.z, b0.w, b1.x, b1.y, b1.z, b1.w};
#pragma unroll
            for (int i = 0; i < 8; i++)
#pragma unroll
                for (int j = 0; j < 8; j++)
                    acc[i][j] = fmaf(a[i], b[j], acc[i][j]);
        }
    }
}

// ---------------- Kernel 1: fused QKV projection (head-permuted output) ------
// grid (8, 32, 3), block 256.  z selects {Q,K,V}.
__global__ __launch_bounds__(256, 2)
void qkv_gemm(const float* __restrict__ X, const float* __restrict__ WQ,
              const float* __restrict__ WK, const float* __restrict__ WV)
{
    const float* W = (blockIdx.z == 0) ? WQ : (blockIdx.z == 1) ? WK : WV;
    float* OUT     = (blockIdx.z == 0) ? g_Q : (blockIdx.z == 1) ? g_K : g_V;

    float acc[8][8];
#pragma unroll
    for (int i = 0; i < 8; i++)
#pragma unroll
        for (int j = 0; j < 8; j++) acc[i][j] = 0.f;

    sgemm_tile128(X, W, acc);

    const int tid = threadIdx.x;
    const int ty = tid >> 4, tx = tid & 15;
    const int mbase = blockIdx.y * 128 + ty * 8;
    const int nbase = blockIdx.x * 128 + tx * 8;
#pragma unroll
    for (int i = 0; i < 8; i++) {
        const int m = mbase + i;
        const int b = m >> 11;        // /2048
        const int n = m & 2047;
#pragma unroll
        for (int j = 0; j < 8; j++) {
            const int c = nbase + j;
            const int h = c >> 6;     // /64
            const int d = c & 63;
            OUT[(((b << 4) + h) * Nv + n) * 64 + d] = acc[i][j];
        }
    }
}

// ---------------- Kernel 2: block-mean pooling of Q and K --------------------
// grid = B*H*Tr = 2048, block = 64 (one thread per d)
__global__ void pool_kernel(void)
{
    const int blk = blockIdx.x;          // bh*64 + t
    const int d   = threadIdx.x;
    const int t   = blk & (TRv - 1);
    const int bh  = blk / TRv;
    const float* Qb = g_Q + (bh * Nv + t * 32) * 64 + d;
    const float* Kb = g_K + (bh * Nv + t * 32) * 64 + d;
    float sq = 0.f, sk = 0.f;
#pragma unroll
    for (int r = 0; r < 32; r++) {
        sq += Qb[r * 64];
        sk += Kb[r * 64];
    }
    g_Qp[blk * 64 + d] = sq * (1.f / 32.f);
    g_Kp[blk * 64 + d] = sk * (1.f / 32.f);
}

// ---------------- Kernel 3: block score matrix S[t,c] ------------------------
// grid = 64 (one per t), block = 64 (one per c). Mean over (b,h) folded:
// constant scale does not change top-k, so we just sum.
__global__ void score_kernel(void)
{
    __shared__ float Qall[32][64];       // Qp[bh][t][*] for this t, all bh
    const int t = blockIdx.x;
    const int c = threadIdx.x;
    for (int e = c; e < 32 * 64; e += 64) {
        int bh = e >> 6, d = e & 63;
        Qall[bh][d] = g_Qp[(bh * TRv + t) * 64 + d];
    }
    __syncthreads();
    float s = 0.f;
    for (int bh = 0; bh < 32; bh++) {
        const float4* kp = reinterpret_cast<const float4*>(g_Kp + (bh * TRv + c) * 64);
        const float*  qp = Qall[bh];
#pragma unroll
        for (int d4 = 0; d4 < 16; d4++) {
            float4 kv = kp[d4];
            s = fmaf(qp[d4 * 4 + 0], kv.x, s);
            s = fmaf(qp[d4 * 4 + 1], kv.y, s);
            s = fmaf(qp[d4 * 4 + 2], kv.z, s);
            s = fmaf(qp[d4 * 4 + 3], kv.w, s);
        }
    }
    g_S[t * TRv + c] = s;
}

// ---------------- Kernel 4: top-12 per row (set only; order irrelevant) ------
__global__ void topk_kernel(void)
{
    const int t = threadIdx.x;           // 64 threads
    if (t >= TRv) return;
    float v[TRv];
#pragma unroll
    for (int c = 0; c < TRv; c++) v[c] = g_S[t * TRv + c];
    for (int j = 0; j < KSEL; j++) {
        int best = 0;
        float bv = v[0];
#pragma unroll
        for (int c = 1; c < TRv; c++) {
            if (v[c] > bv) { bv = v[c]; best = c; }
        }
        g_idx[t * KSEL + j] = best;
        v[best] = -3.0e38f;
    }
}

// ---------------- Kernel 5: sparse attention (flash-style) -------------------
// grid (Tr=64, H=16, B=2), block 256.
// Each block: Q tile [32,64] x 12 selected K/V blocks, online softmax.
__global__ __launch_bounds__(256, 1)
void attn_kernel(void)
{
    __shared__ float Qs[32][68];
    __shared__ float Ks[32][68];
    __shared__ float Vs[32][68];
    __shared__ float Sb[32][33];

    const int t  = blockIdx.x;
    const int h  = blockIdx.y;
    const int b  = blockIdx.z;
    const int bh = b * Hv + h;
    const int tid = threadIdx.x;

    // load Q tile (2048 floats)
    const float* Qg = g_Q + (bh * Nv + t * 32) * 64;
    for (int e = tid; e < 512; e += 256) {
        float4 v = *reinterpret_cast<const float4*>(Qg + e * 4);
        int r = e >> 4, c = (e & 15) * 4;
        *reinterpret_cast<float4*>(&Qs[r][c]) = v;
    }

    const int q     = tid >> 3;      // 0..31: query row owned
    const int sub   = tid & 7;       // 0..7
    const int dbase = sub * 8;       // 8 output dims owned
    const int kk0   = sub;           // S-compute column phase

    float m_run = -3.0e38f;
    float l_run = 0.f;
    float oacc[8];
#pragma unroll
    for (int i = 0; i < 8; i++) oacc[i] = 0.f;

    for (int j = 0; j < KSEL; j++) {
        const int c = g_idx[t * KSEL + j];
        const float* Kg = g_K + (bh * Nv + c * 32) * 64;
        const float* Vg = g_V + (bh * Nv + c * 32) * 64;
        __syncthreads();   // previous iteration's readers done
        for (int e = tid; e < 512; e += 256) {
            int r = e >> 4, cc = (e & 15) * 4;
            *reinterpret_cast<float4*>(&Ks[r][cc]) =
                *reinterpret_cast<const float4*>(Kg + e * 4);
            *reinterpret_cast<float4*>(&Vs[r][cc]) =
                *reinterpret_cast<const float4*>(Vg + e * 4);
        }
        __syncthreads();

        // S block: 4 columns per thread (kk0, kk0+8, kk0+16, kk0+24)
        float s0 = 0.f, s1 = 0.f, s2 = 0.f, s3 = 0.f;
#pragma unroll 8
        for (int d = 0; d < 64; d++) {
            float aq = Qs[q][d];
            s0 = fmaf(aq, Ks[kk0][d],      s0);
            s1 = fmaf(aq, Ks[kk0 + 8][d],  s1);
            s2 = fmaf(aq, Ks[kk0 + 16][d], s2);
            s3 = fmaf(aq, Ks[kk0 + 24][d], s3);
        }
        Sb[q][kk0]      = s0 * 0.125f;
        Sb[q][kk0 + 8]  = s1 * 0.125f;
        Sb[q][kk0 + 16] = s2 * 0.125f;
        Sb[q][kk0 + 24] = s3 * 0.125f;
        __syncthreads();

        // online softmax update (redundant within the 8-thread row group)
        float mloc = -3.0e38f;
#pragma unroll
        for (int kk = 0; kk < 32; kk++) mloc = fmaxf(mloc, Sb[q][kk]);
        const float m_new = fmaxf(m_run, mloc);
        const float corr  = __expf(m_run - m_new);
        l_run *= corr;
#pragma unroll
        for (int dd = 0; dd < 8; dd++) oacc[dd] *= corr;
#pragma unroll
        for (int kk = 0; kk < 32; kk++) {
            float p = __expf(Sb[q][kk] - m_new);
            l_run += p;
            float4 v0 = *reinterpret_cast<const float4*>(&Vs[kk][dbase]);
            float4 v1 = *reinterpret_cast<const float4*>(&Vs[kk][dbase + 4]);
            oacc[0] = fmaf(p, v0.x, oacc[0]);
            oacc[1] = fmaf(p, v0.y, oacc[1]);
            oacc[2] = fmaf(p, v0.z, oacc[2]);
            oacc[3] = fmaf(p, v0.w, oacc[3]);
            oacc[4] = fmaf(p, v1.x, oacc[4]);
            oacc[5] = fmaf(p, v1.y, oacc[5]);
            oacc[6] = fmaf(p, v1.z, oacc[6]);
            oacc[7] = fmaf(p, v1.w, oacc[7]);
        }
        m_run = m_new;
    }

    const float inv_l = 1.0f / l_run;
    float* Og = g_O + (((b * Nv) + t * 32 + q) * Hv + h) * 64 + dbase;
#pragma unroll
    for (int dd = 0; dd < 8; dd++) Og[dd] = oacc[dd] * inv_l;
}

// ---------------- Kernel 6: output projection O @ W_O ------------------------
// grid (8, 32), block 256.
__global__ __launch_bounds__(256, 2)
void out_gemm(const float* __restrict__ WO, float* __restrict__ out)
{
    float acc[8][8];
#pragma unroll
    for (int i = 0; i < 8; i++)
#pragma unroll
        for (int j = 0; j < 8; j++) acc[i][j] = 0.f;

    sgemm_tile128(g_O, WO, acc);

    const int tid = threadIdx.x;
    const int ty = tid >> 4, tx = tid & 15;
    const int mbase = blockIdx.y * 128 + ty * 8;
    const int nbase = blockIdx.x * 128 + tx * 8;
#pragma unroll
    for (int i = 0; i < 8; i++) {
        float* row = out + (mbase + i) * 1024 + nbase;
        float4 r0 = make_float4(acc[i][0], acc[i][1], acc[i][2], acc[i][3]);
        float4 r1 = make_float4(acc[i][4], acc[i][5], acc[i][6], acc[i][7]);
        *reinterpret_cast<float4*>(row)     = r0;
        *reinterpret_cast<float4*>(row + 4) = r1;
    }
}

// ---------------- launch ------------------------------------------------------
extern "C" void kernel_launch(void* const* d_in, const int* in_sizes, int n_in,
                              void* d_out, int out_size)
{
    const float* x  = (const float*)d_in[0];
    const float* wq = (const float*)d_in[1];
    const float* wk = (const float*)d_in[2];
    const float* wv = (const float*)d_in[3];
    const float* wo = (const float*)d_in[4];
    float* out = (float*)d_out;

    qkv_gemm<<<dim3(8, 32, 3), 256>>>(x, wq, wk, wv);
    pool_kernel<<<Bv * Hv * TRv, 64>>>();
    score_kernel<<<TRv, 64>>>();
    topk_kernel<<<1, 64>>>();
    attn_kernel<<<dim3(TRv, Hv, Bv), 256>>>();
    out_gemm<<<dim3(8, 32), 256>>>(wo, out);
}

// round 6
// speedup vs baseline: 1.5079x; 1.5079x over previous
#include <cuda_runtime.h>
#include <cuda_bf16.h>
#include <cstdint>

// Problem constants
#define Bv   2
#define Nv   2048
#define Ev   1024
#define Hv   16
#define Dv   64
#define TRv  64          // Tr = Tc = 64
#define KSEL 12          // int(0.2 * 64)
#define KP   3072        // augmented K for split-bf16 GEMM

// ---------------- scratch (static device globals; no allocation) -------------
__device__ float g_Q[Bv * Hv * Nv * Dv];   // [bh,n,d] fp32 (for attention + pooling)
__device__ float g_K[Bv * Hv * Nv * Dv];
__device__ float g_V[Bv * Hv * Nv * Dv];
__device__ __nv_bfloat16 g_A1[4096 * KP];  // split x:  [hi | hi | lo] along k
__device__ __nv_bfloat16 g_Wc[4][KP * 1024]; // split W: rows [hi ; lo ; hi]
__device__ __nv_bfloat16 g_A2[4096 * KP];  // split attention output
__device__ float g_Qp[Bv * Hv * TRv * Dv];
__device__ float g_Kp[Bv * Hv * TRv * Dv];
__device__ float g_S[TRv * TRv];
__device__ int   g_idx[TRv * KSEL];

// ---------------- bf16 split helpers -----------------------------------------
__device__ __forceinline__ void split_bf16(float v, __nv_bfloat16& hi, __nv_bfloat16& lo)
{
    hi = __float2bfloat16(v);
    lo = __float2bfloat16(v - __bfloat162float(hi));
}

// ---------------- conversion kernels -----------------------------------------
// x [4096,1024] fp32 -> g_A1 [4096,3072] bf16  (cols: 0-1023 hi, 1024-2047 hi, 2048-3071 lo)
__global__ void convert_x(const float* __restrict__ X)
{
    const int i = blockIdx.x * 256 + threadIdx.x;   // 0 .. 4M-1
    const float v = X[i];
    __nv_bfloat16 hi, lo; split_bf16(v, hi, lo);
    const int r = i >> 10, c = i & 1023;
    __nv_bfloat16* row = g_A1 + (size_t)r * KP;
    row[c] = hi; row[c + 1024] = hi; row[c + 2048] = lo;
}

// W [1024,1024] fp32 -> g_Wc[w] [3072,1024] bf16 (rows: hi ; lo ; hi)
__global__ void convert_w(const float* __restrict__ W0, const float* __restrict__ W1,
                          const float* __restrict__ W2, const float* __restrict__ W3)
{
    const float* W = (blockIdx.y == 0) ? W0 : (blockIdx.y == 1) ? W1 :
                     (blockIdx.y == 2) ? W2 : W3;
    const int i = blockIdx.x * 256 + threadIdx.x;   // 0 .. 1M-1
    const float v = W[i];
    __nv_bfloat16 hi, lo; split_bf16(v, hi, lo);
    const int r = i >> 10, c = i & 1023;
    __nv_bfloat16* dst = g_Wc[blockIdx.y];
    dst[(size_t)r * 1024 + c]          = hi;
    dst[(size_t)(r + 1024) * 1024 + c] = lo;
    dst[(size_t)(r + 2048) * 1024 + c] = hi;
}

// ---------------- tensor-core GEMM core (128x128 block, K'=3072) --------------
__device__ __forceinline__ uint32_t sptr(const void* p)
{
    return (uint32_t)__cvta_generic_to_shared(p);
}
__device__ __forceinline__ void ldm4(uint32_t (&r)[4], const void* p)
{
    asm volatile("ldmatrix.sync.aligned.m8n8.x4.shared.b16 {%0,%1,%2,%3}, [%4];"
                 : "=r"(r[0]), "=r"(r[1]), "=r"(r[2]), "=r"(r[3]) : "r"(sptr(p)));
}
__device__ __forceinline__ void ldm4t(uint32_t (&r)[4], const void* p)
{
    asm volatile("ldmatrix.sync.aligned.m8n8.x4.trans.shared.b16 {%0,%1,%2,%3}, [%4];"
                 : "=r"(r[0]), "=r"(r[1]), "=r"(r[2]), "=r"(r[3]) : "r"(sptr(p)));
}
__device__ __forceinline__ void mma16816(float (&c)[4], const uint32_t (&a)[4],
                                         uint32_t b0, uint32_t b1)
{
    asm volatile(
        "mma.sync.aligned.m16n8k16.row.col.f32.bf16.bf16.f32 "
        "{%0,%1,%2,%3}, {%4,%5,%6,%7}, {%8,%9}, {%0,%1,%2,%3};"
        : "+f"(c[0]), "+f"(c[1]), "+f"(c[2]), "+f"(c[3])
        : "r"(a[0]), "r"(a[1]), "r"(a[2]), "r"(a[3]), "r"(b0), "r"(b1));
}

// A [4096, KP] bf16 row-major; W [KP, 1024] bf16 row-major.
// Block tile 128x128, 8 warps (2x4), warp tile 64x32, BK=32, double-buffered.
__device__ __forceinline__ void mm_core(const __nv_bfloat16* __restrict__ A,
                                        const __nv_bfloat16* __restrict__ W,
                                        float acc[4][4][4])
{
    __shared__ __align__(16) __nv_bfloat16 As[2][128][40];   // pad: 40 halfs = 80B stride
    __shared__ __align__(16) __nv_bfloat16 Bs[2][32][136];   // pad: 136 halfs = 272B stride

    const int tid  = threadIdx.x;
    const int lane = tid & 31;
    const int wid  = tid >> 5;
    const int wm   = wid >> 2;           // 0..1
    const int wn   = wid & 3;            // 0..3
    const int mBase = blockIdx.y * 128;
    const int nBase = blockIdx.x * 128;

    // global load pointers (each thread: 2 x 16B for A, 2 x 16B for B per stage)
    const __nv_bfloat16* Ag = A + (size_t)(mBase + (tid >> 2)) * KP + (tid & 3) * 8;
    const __nv_bfloat16* Bg = W + (size_t)(tid >> 4) * 1024 + nBase + (tid & 15) * 8;

    const int a_r0 = tid >> 2;           // 0..63  (row1 = +64)
    const int a_c  = (tid & 3) * 8;
    const int b_r0 = tid >> 4;           // 0..15  (row1 = +16)
    const int b_c  = (tid & 15) * 8;

    uint4 ra0 = *(const uint4*)(Ag);
    uint4 ra1 = *(const uint4*)(Ag + (size_t)64 * KP);
    uint4 rb0 = *(const uint4*)(Bg);
    uint4 rb1 = *(const uint4*)(Bg + 16 * 1024);

    *(uint4*)&As[0][a_r0][a_c]      = ra0;
    *(uint4*)&As[0][a_r0 + 64][a_c] = ra1;
    *(uint4*)&Bs[0][b_r0][b_c]      = rb0;
    *(uint4*)&Bs[0][b_r0 + 16][b_c] = rb1;
    __syncthreads();

    const int NKT = KP / 32;             // 96
    for (int kt = 0; kt < NKT; kt++) {
        const int p = kt & 1;
        if (kt < NKT - 1) {
            const __nv_bfloat16* Agk = Ag + (kt + 1) * 32;
            const __nv_bfloat16* Bgk = Bg + (size_t)(kt + 1) * 32 * 1024;
            ra0 = *(const uint4*)(Agk);
            ra1 = *(const uint4*)(Agk + (size_t)64 * KP);
            rb0 = *(const uint4*)(Bgk);
            rb1 = *(const uint4*)(Bgk + 16 * 1024);
        }

#pragma unroll
        for (int ks = 0; ks < 32; ks += 16) {
            uint32_t af[4][4];
#pragma unroll
            for (int mt = 0; mt < 4; mt++)
                ldm4(af[mt], &As[p][wm * 64 + mt * 16 + (lane & 15)][ks + (lane >> 4) * 8]);
            uint32_t bf[2][4];
#pragma unroll
            for (int jp = 0; jp < 2; jp++)
                ldm4t(bf[jp], &Bs[p][ks + ((lane >> 3) & 1) * 8 + (lane & 7)]
                                    [wn * 32 + jp * 16 + (lane >> 4) * 8]);
#pragma unroll
            for (int mt = 0; mt < 4; mt++)
#pragma unroll
                for (int nt = 0; nt < 4; nt++)
                    mma16816(acc[mt][nt], af[mt],
                             bf[nt >> 1][(nt & 1) * 2], bf[nt >> 1][(nt & 1) * 2 + 1]);
        }

        if (kt < NKT - 1) {
            const int q = 1 - p;
            *(uint4*)&As[q][a_r0][a_c]      = ra0;
            *(uint4*)&As[q][a_r0 + 64][a_c] = ra1;
            *(uint4*)&Bs[q][b_r0][b_c]      = rb0;
            *(uint4*)&Bs[q][b_r0 + 16][b_c] = rb1;
            __syncthreads();
        }
    }
}

// ---------------- Kernel: QKV projection (head-permuted epilogue) ------------
// grid (8, 32, 3), block 256
__global__ __launch_bounds__(256)
void mm_qkv(void)
{
    const __nv_bfloat16* W = g_Wc[blockIdx.z];
    float* OUT = (blockIdx.z == 0) ? g_Q : (blockIdx.z == 1) ? g_K : g_V;

    float acc[4][4][4];
#pragma unroll
    for (int a = 0; a < 4; a++)
#pragma unroll
        for (int b = 0; b < 4; b++)
#pragma unroll
            for (int c = 0; c < 4; c++) acc[a][b][c] = 0.f;

    mm_core(g_A1, W, acc);

    const int lane = threadIdx.x & 31, wid = threadIdx.x >> 5;
    const int wm = wid >> 2, wn = wid & 3;
    const int mBase = blockIdx.y * 128 + wm * 64;
    const int nBase = blockIdx.x * 128 + wn * 32;
#pragma unroll
    for (int mt = 0; mt < 4; mt++) {
#pragma unroll
        for (int nt = 0; nt < 4; nt++) {
            const int gc = nBase + nt * 8 + (lane & 3) * 2;
            const int h = gc >> 6, d = gc & 63;
#pragma unroll
            for (int half = 0; half < 2; half++) {
                const int gr = mBase + mt * 16 + (lane >> 2) + half * 8;
                const int b = gr >> 11, n = gr & 2047;
                float2 v = make_float2(acc[mt][nt][half * 2], acc[mt][nt][half * 2 + 1]);
                *(float2*)&OUT[(((size_t)(b * Hv + h)) * Nv + n) * 64 + d] = v;
            }
        }
    }
}

// ---------------- Kernel: output projection ----------------------------------
// grid (8, 32), block 256
__global__ __launch_bounds__(256)
void mm_out(float* __restrict__ out)
{
    float acc[4][4][4];
#pragma unroll
    for (int a = 0; a < 4; a++)
#pragma unroll
        for (int b = 0; b < 4; b++)
#pragma unroll
            for (int c = 0; c < 4; c++) acc[a][b][c] = 0.f;

    mm_core(g_A2, g_Wc[3], acc);

    const int lane = threadIdx.x & 31, wid = threadIdx.x >> 5;
    const int wm = wid >> 2, wn = wid & 3;
    const int mBase = blockIdx.y * 128 + wm * 64;
    const int nBase = blockIdx.x * 128 + wn * 32;
#pragma unroll
    for (int mt = 0; mt < 4; mt++) {
#pragma unroll
        for (int nt = 0; nt < 4; nt++) {
            const int gc = nBase + nt * 8 + (lane & 3) * 2;
#pragma unroll
            for (int half = 0; half < 2; half++) {
                const int gr = mBase + mt * 16 + (lane >> 2) + half * 8;
                float2 v = make_float2(acc[mt][nt][half * 2], acc[mt][nt][half * 2 + 1]);
                *(float2*)&out[(size_t)gr * 1024 + gc] = v;
            }
        }
    }
}

// ---------------- Kernel: block-mean pooling of Q and K ----------------------
__global__ void pool_kernel(void)
{
    const int blk = blockIdx.x;          // bh*64 + t
    const int d   = threadIdx.x;
    const int t   = blk & (TRv - 1);
    const int bh  = blk / TRv;
    const float* Qb = g_Q + ((size_t)bh * Nv + t * 32) * 64 + d;
    const float* Kb = g_K + ((size_t)bh * Nv + t * 32) * 64 + d;
    float sq = 0.f, sk = 0.f;
#pragma unroll
    for (int r = 0; r < 32; r++) { sq += Qb[r * 64]; sk += Kb[r * 64]; }
    g_Qp[blk * 64 + d] = sq * (1.f / 32.f);
    g_Kp[blk * 64 + d] = sk * (1.f / 32.f);
}

// ---------------- Kernel: block score matrix ---------------------------------
__global__ void score_kernel(void)
{
    __shared__ __align__(16) float Qall[32][64];
    const int t = blockIdx.x;
    const int c = threadIdx.x;
    for (int e = c; e < 32 * 64; e += 64) {
        int bh = e >> 6, d = e & 63;
        Qall[bh][d] = g_Qp[(bh * TRv + t) * 64 + d];
    }
    __syncthreads();
    float s = 0.f;
    for (int bh = 0; bh < 32; bh++) {
        const float4* kp = reinterpret_cast<const float4*>(g_Kp + (bh * TRv + c) * 64);
        const float*  qp = Qall[bh];
#pragma unroll
        for (int d4 = 0; d4 < 16; d4++) {
            float4 kv = kp[d4];
            s = fmaf(qp[d4 * 4 + 0], kv.x, s);
            s = fmaf(qp[d4 * 4 + 1], kv.y, s);
            s = fmaf(qp[d4 * 4 + 2], kv.z, s);
            s = fmaf(qp[d4 * 4 + 3], kv.w, s);
        }
    }
    g_S[t * TRv + c] = s;
}

// ---------------- Kernel: top-12 per row -------------------------------------
__global__ void topk_kernel(void)
{
    const int t = threadIdx.x;
    if (t >= TRv) return;
    float v[TRv];
#pragma unroll
    for (int c = 0; c < TRv; c++) v[c] = g_S[t * TRv + c];
    for (int j = 0; j < KSEL; j++) {
        int best = 0; float bv = v[0];
#pragma unroll
        for (int c = 1; c < TRv; c++)
            if (v[c] > bv) { bv = v[c]; best = c; }
        g_idx[t * KSEL + j] = best;
        v[best] = -3.0e38f;
    }
}

// ---------------- Kernel: sparse attention (flash-style) ---------------------
// grid (Tr=64, H=16, B=2), block 256. Epilogue writes split-bf16 into g_A2.
__global__ __launch_bounds__(256, 1)
void attn_kernel(void)
{
    __shared__ __align__(16) float Qs[32][68];
    __shared__ __align__(16) float Ks[32][68];
    __shared__ __align__(16) float Vs[32][68];
    __shared__ __align__(16) float Sb[32][33];

    const int t  = blockIdx.x;
    const int h  = blockIdx.y;
    const int b  = blockIdx.z;
    const int bh = b * Hv + h;
    const int tid = threadIdx.x;

    const float* Qg = g_Q + ((size_t)bh * Nv + t * 32) * 64;
    for (int e = tid; e < 512; e += 256) {
        float4 v = *reinterpret_cast<const float4*>(Qg + e * 4);
        int r = e >> 4, c = (e & 15) * 4;
        *reinterpret_cast<float4*>(&Qs[r][c]) = v;
    }

    const int q     = tid >> 3;      // 0..31
    const int sub   = tid & 7;       // 0..7
    const int dbase = sub * 8;
    const int kk0   = sub;

    float m_run = -3.0e38f;
    float l_run = 0.f;
    float oacc[8];
#pragma unroll
    for (int i = 0; i < 8; i++) oacc[i] = 0.f;

    for (int j = 0; j < KSEL; j++) {
        const int c = g_idx[t * KSEL + j];
        const float* Kg = g_K + ((size_t)bh * Nv + c * 32) * 64;
        const float* Vg = g_V + ((size_t)bh * Nv + c * 32) * 64;
        __syncthreads();
        for (int e = tid; e < 512; e += 256) {
            int r = e >> 4, cc = (e & 15) * 4;
            *reinterpret_cast<float4*>(&Ks[r][cc]) =
                *reinterpret_cast<const float4*>(Kg + e * 4);
            *reinterpret_cast<float4*>(&Vs[r][cc]) =
                *reinterpret_cast<const float4*>(Vg + e * 4);
        }
        __syncthreads();

        // scores for this thread's 4 columns
        float s0 = 0.f, s1 = 0.f, s2 = 0.f, s3 = 0.f;
#pragma unroll 8
        for (int d = 0; d < 64; d++) {
            float aq = Qs[q][d];
            s0 = fmaf(aq, Ks[kk0][d],      s0);
            s1 = fmaf(aq, Ks[kk0 + 8][d],  s1);
            s2 = fmaf(aq, Ks[kk0 + 16][d], s2);
            s3 = fmaf(aq, Ks[kk0 + 24][d], s3);
        }
        s0 *= 0.125f; s1 *= 0.125f; s2 *= 0.125f; s3 *= 0.125f;

        // block max across the 8-lane row group (lanes differ in bits 0..2)
        float mloc = fmaxf(fmaxf(s0, s1), fmaxf(s2, s3));
        mloc = fmaxf(mloc, __shfl_xor_sync(0xffffffffu, mloc, 1));
        mloc = fmaxf(mloc, __shfl_xor_sync(0xffffffffu, mloc, 2));
        mloc = fmaxf(mloc, __shfl_xor_sync(0xffffffffu, mloc, 4));
        const float m_new = fmaxf(m_run, mloc);
        const float corr  = __expf(m_run - m_new);

        const float p0 = __expf(s0 - m_new);
        const float p1 = __expf(s1 - m_new);
        const float p2 = __expf(s2 - m_new);
        const float p3 = __expf(s3 - m_new);
        Sb[q][kk0]      = p0;
        Sb[q][kk0 + 8]  = p1;
        Sb[q][kk0 + 16] = p2;
        Sb[q][kk0 + 24] = p3;

        float ls = p0 + p1 + p2 + p3;
        ls += __shfl_xor_sync(0xffffffffu, ls, 1);
        ls += __shfl_xor_sync(0xffffffffu, ls, 2);
        ls += __shfl_xor_sync(0xffffffffu, ls, 4);
        l_run = l_run * corr + ls;
#pragma unroll
        for (int dd = 0; dd < 8; dd++) oacc[dd] *= corr;
        __syncwarp();

#pragma unroll
        for (int kk = 0; kk < 32; kk++) {
            float p = Sb[q][kk];
            float4 v0 = *reinterpret_cast<const float4*>(&Vs[kk][dbase]);
            float4 v1 = *reinterpret_cast<const float4*>(&Vs[kk][dbase + 4]);
            oacc[0] = fmaf(p, v0.x, oacc[0]);
            oacc[1] = fmaf(p, v0.y, oacc[1]);
            oacc[2] = fmaf(p, v0.z, oacc[2]);
            oacc[3] = fmaf(p, v0.w, oacc[3]);
            oacc[4] = fmaf(p, v1.x, oacc[4]);
            oacc[5] = fmaf(p, v1.y, oacc[5]);
            oacc[6] = fmaf(p, v1.z, oacc[6]);
            oacc[7] = fmaf(p, v1.w, oacc[7]);
        }
        m_run = m_new;
    }

    // epilogue: split-bf16 write into g_A2 [row, 3072] = [hi | hi | lo]
    const float inv_l = 1.0f / l_run;
    const int row  = b * Nv + t * 32 + q;
    const int colb = h * 64 + dbase;
    alignas(16) __nv_bfloat16 hi8[8];
    alignas(16) __nv_bfloat16 lo8[8];
#pragma unroll
    for (int dd = 0; dd < 8; dd++) {
        float o = oacc[dd] * inv_l;
        split_bf16(o, hi8[dd], lo8[dd]);
    }
    __nv_bfloat16* rp = g_A2 + (size_t)row * KP + colb;
    *(uint4*)(rp)        = *(const uint4*)hi8;
    *(uint4*)(rp + 1024) = *(const uint4*)hi8;
    *(uint4*)(rp + 2048) = *(const uint4*)lo8;
}

// ---------------- launch ------------------------------------------------------
extern "C" void kernel_launch(void* const* d_in, const int* in_sizes, int n_in,
                              void* d_out, int out_size)
{
    const float* x  = (const float*)d_in[0];
    const float* wq = (const float*)d_in[1];
    const float* wk = (const float*)d_in[2];
    const float* wv = (const float*)d_in[3];
    const float* wo = (const float*)d_in[4];
    float* out = (float*)d_out;

    convert_w<<<dim3(4096, 4), 256>>>(wq, wk, wv, wo);
    convert_x<<<16384, 256>>>(x);
    mm_qkv<<<dim3(8, 32, 3), 256>>>();
    pool_kernel<<<Bv * Hv * TRv, 64>>>();
    score_kernel<<<TRv, 64>>>();
    topk_kernel<<<1, 64>>>();
    attn_kernel<<<dim3(TRv, Hv, Bv), 256>>>();
    mm_out<<<dim3(8, 32), 256>>>(out);
}